// round 4
// baseline (speedup 1.0000x reference)
#include <cuda_runtime.h>
#include <cuda_bf16.h>
#include <cuda_fp8.h>
#include <cstdint>

#define BATCH 32768
#define DDIM  256
#define KDIM  1024
#define ADIM  32

#define TM      128
#define TN      128
#define THREADS 512
#define NBLOCKS (BATCH / TM)
#define TOTCH   16          // 2 nets * 8 chunks of 128 centers
#define KSTEPS  8           // DDIM / 32 fp8 per MMA k-step
#define PHI_STRIDE 272      // bytes per phi row (16B aligned, bank-rotating)

// ---- SMEM layout (bytes) ----
#define SA    0             // A tile 128x256 fp8 swizzled   (32768)
#define SB0   32768         // B tile buf0                    (32768)
#define SB1   65536         // B tile buf1                    (32768)
#define SPHI  98304         // phi tile 128 x 272B            (34816)
#define SX2   133120        // x2 per row                     (512)
#define SMEM_TOTAL (133120 + 512)

// ---- device scratch (static, no runtime alloc) ----
__device__ unsigned char g_c_f8[(size_t)2 * KDIM * DDIM];  // [mean_C; std_C] e4m3
__device__ float g_c2[2 * KDIM];
__device__ float g_i2s[2 * KDIM];

// ============ helpers ============
__device__ __forceinline__ uint32_t smem_u32_of(const void* p) {
    uint32_t a;
    asm("{ .reg .u64 t; cvta.to.shared.u64 t, %1; cvt.u32.u64 %0, t; }" : "=r"(a) : "l"(p));
    return a;
}

__device__ __forceinline__ void ldmatrix_x4(uint32_t* r, uint32_t addr) {
    asm volatile("ldmatrix.sync.aligned.m8n8.x4.shared.b16 {%0,%1,%2,%3}, [%4];"
                 : "=r"(r[0]), "=r"(r[1]), "=r"(r[2]), "=r"(r[3]) : "r"(addr));
}

__device__ __forceinline__ void mma_fp8(float* d, const uint32_t* a, uint32_t b0, uint32_t b1) {
    asm volatile("mma.sync.aligned.m16n8k32.row.col.f32.e4m3.e4m3.f32 "
                 "{%0,%1,%2,%3}, {%4,%5,%6,%7}, {%8,%9}, {%0,%1,%2,%3};"
                 : "+f"(d[0]), "+f"(d[1]), "+f"(d[2]), "+f"(d[3])
                 : "r"(a[0]), "r"(a[1]), "r"(a[2]), "r"(a[3]), "r"(b0), "r"(b1));
}

#define CP_ASYNC16(dst, src) \
    asm volatile("cp.async.cg.shared.global [%0], [%1], 16;" :: "r"(dst), "l"(src) : "memory")
#define CP_COMMIT()   asm volatile("cp.async.commit_group;" ::: "memory")
#define CP_WAIT_ALL() asm volatile("cp.async.wait_all;" ::: "memory")

__device__ __forceinline__ uint32_t pack_bf2(float lo, float hi) {
    __nv_bfloat162 h = __floats2bfloat162_rn(lo, hi);
    return reinterpret_cast<uint32_t&>(h);
}

__device__ __forceinline__ uint32_t pack_f8x4(float a, float b, float c, float d) {
    uint32_t lo = __nv_cvt_float2_to_fp8x2(make_float2(a, b), __NV_SATFINITE, __NV_E4M3);
    uint32_t hi = __nv_cvt_float2_to_fp8x2(make_float2(c, d), __NV_SATFINITE, __NV_E4M3);
    return lo | (hi << 16);
}

// fp8 tile byte offset with XOR swizzle on 16B granules (256B rows, 16 granules)
__device__ __forceinline__ uint32_t tile_off8(int row, int c16) {
    return ((uint32_t)row << 8) + (((uint32_t)(c16 ^ (row & 7))) << 4);
}

// ============ prep kernel: C -> e4m3, c2 = ||c||^2, i2s = 1/(2|sigma|) ============
__global__ void prep_scales(const float* __restrict__ mC, const float* __restrict__ sC,
                            const float* __restrict__ mS, const float* __restrict__ sS) {
    int w = (blockIdx.x * blockDim.x + threadIdx.x) >> 5;
    int lane = threadIdx.x & 31;
    if (w >= 2 * KDIM) return;
    int net = w >> 10, k = w & (KDIM - 1);
    const float* C = net ? sC : mC;
    const float4* cp = (const float4*)(C + (size_t)k * DDIM);
    float4 v0 = cp[lane * 2], v1 = cp[lane * 2 + 1];
    float s = v0.x*v0.x + v0.y*v0.y + v0.z*v0.z + v0.w*v0.w
            + v1.x*v1.x + v1.y*v1.y + v1.z*v1.z + v1.w*v1.w;
    uint2 u;
    u.x = pack_f8x4(v0.x, v0.y, v0.z, v0.w);
    u.y = pack_f8x4(v1.x, v1.y, v1.z, v1.w);
    ((uint2*)(g_c_f8 + (size_t)w * DDIM))[lane] = u;
    #pragma unroll
    for (int o = 16; o; o >>= 1) s += __shfl_xor_sync(0xffffffffu, s, o);
    if (lane == 0) {
        g_c2[w] = s;
        float sg = net ? sS[k] : mS[k];
        g_i2s[w] = 1.0f / (2.0f * fabsf(sg));
    }
}

// ============ main kernel ============
__device__ __forceinline__ void issue_B(uint32_t sb, int chunk, int tid) {
    const char* src = (const char*)g_c_f8 + (size_t)chunk * (TN * DDIM);
    #pragma unroll
    for (int it = 0; it < 4; ++it) {
        int i = tid + it * THREADS;          // 2048 granules of 16B
        int row = i >> 4, c16 = i & 15;
        CP_ASYNC16(sb + tile_off8(row, c16), src + i * 16);
    }
    CP_COMMIT();
}

__global__ void __launch_bounds__(THREADS, 1)
rbf_main(const float* __restrict__ obs,
         const float* __restrict__ mean_w, const float* __restrict__ mean_b,
         const float* __restrict__ std_w,  const float* __restrict__ std_b,
         float* __restrict__ out) {
    extern __shared__ char smem[];
    const uint32_t su = smem_u32_of(smem);
    const int tid  = threadIdx.x;
    const int lane = tid & 31;
    const int wid  = tid >> 5;
    const int wm   = wid & 3;          // M warp (rows 32*wm)
    const int wn   = wid >> 2;         // N warp (cols 32*wn)
    const int mrow0 = wm * 32;
    const int ncol0 = wn * 32;

    // kick off B(0) loads immediately
    issue_B(su + SB0, 0, tid);

    // ---- A tile: fp32 gmem -> e4m3 swizzled SMEM; compute x2 per row ----
    {
        int row = tid >> 2, q = tid & 3;
        const float4* src = (const float4*)(obs + ((size_t)blockIdx.x * TM + row) * DDIM)
                            + q * 16;
        float s = 0.f;
        #pragma unroll
        for (int g = 0; g < 4; ++g) {       // granule = 16 floats -> 16 fp8
            float4 v0 = src[g * 4], v1 = src[g * 4 + 1];
            float4 v2 = src[g * 4 + 2], v3 = src[g * 4 + 3];
            s += v0.x*v0.x + v0.y*v0.y + v0.z*v0.z + v0.w*v0.w
               + v1.x*v1.x + v1.y*v1.y + v1.z*v1.z + v1.w*v1.w
               + v2.x*v2.x + v2.y*v2.y + v2.z*v2.z + v2.w*v2.w
               + v3.x*v3.x + v3.y*v3.y + v3.z*v3.z + v3.w*v3.w;
            uint4 u;
            u.x = pack_f8x4(v0.x, v0.y, v0.z, v0.w);
            u.y = pack_f8x4(v1.x, v1.y, v1.z, v1.w);
            u.z = pack_f8x4(v2.x, v2.y, v2.z, v2.w);
            u.w = pack_f8x4(v3.x, v3.y, v3.z, v3.w);
            *(uint4*)(smem + SA + tile_off8(row, q * 4 + g)) = u;
        }
        s += __shfl_xor_sync(0xffffffffu, s, 1);
        s += __shfl_xor_sync(0xffffffffu, s, 2);
        if (!q) ((float*)(smem + SX2))[row] = s;
    }
    __syncthreads();

    // per-lane x2 values for the 4 row groups this lane's MMA fragments cover
    const int g = lane >> 2;
    float x2r[4];
    {
        const float* sx2 = (const float*)(smem + SX2);
        x2r[0] = sx2[mrow0 + g];
        x2r[1] = sx2[mrow0 + g + 8];
        x2r[2] = sx2[mrow0 + g + 16];
        x2r[3] = sx2[mrow0 + g + 24];
    }

    // per-lane ldmatrix row bases (A absolute, B tile-relative)
    const int lhi = lane >> 4;
    uint32_t abase[2]; int amask[2];
    #pragma unroll
    for (int mf = 0; mf < 2; ++mf) {
        int r = mrow0 + mf * 16 + (lane & 15);
        abase[mf] = su + SA + ((uint32_t)r << 8);
        amask[mf] = r & 7;
    }
    uint32_t bbase[2]; int bmask[2];
    #pragma unroll
    for (int j = 0; j < 2; ++j) {
        int r = ncol0 + j * 16 + (lane & 15);
        bbase[j] = (uint32_t)r << 8;
        bmask[j] = r & 7;
    }

    float acc[ADIM / 2];
    #pragma unroll
    for (int a = 0; a < ADIM / 2; ++a) acc[a] = 0.f;

    const int cl0 = ncol0 + 2 * (lane & 3);
    // phi@w partition: each thread = (row, colhalf, ahalf)
    const int prow    = tid >> 2;
    const int ahalf   = tid & 1;
    const int colhalf = (tid >> 1) & 1;

    for (int t = 0; t < TOTCH; ++t) {
        const uint32_t sb = su + ((t & 1) ? SB1 : SB0);

        CP_WAIT_ALL();
        __syncthreads();                       // B(t) resident, phi(t-1) consumed
        if (t + 1 < TOTCH) issue_B(su + (((t + 1) & 1) ? SB1 : SB0), t + 1, tid);

        // ---- GEMM: obs @ C^T for this 32-col warp chunk (fp8, k=32/step) ----
        float am[2][4][4];
        #pragma unroll
        for (int mf = 0; mf < 2; ++mf)
            #pragma unroll
            for (int nf = 0; nf < 4; ++nf)
                #pragma unroll
                for (int e = 0; e < 4; ++e) am[mf][nf][e] = 0.f;

        uint32_t afr[2][2][4], bfr[2][2][4];
        {   // prefetch k-step 0
            const int c16 = lhi;
            #pragma unroll
            for (int mf = 0; mf < 2; ++mf)
                ldmatrix_x4(afr[0][mf], abase[mf] + (((uint32_t)(c16 ^ amask[mf])) << 4));
            #pragma unroll
            for (int j = 0; j < 2; ++j)
                ldmatrix_x4(bfr[0][j], sb + bbase[j] + (((uint32_t)(c16 ^ bmask[j])) << 4));
        }
        #pragma unroll
        for (int ks = 0; ks < KSTEPS; ++ks) {
            const int cur = ks & 1, nxt = cur ^ 1;
            if (ks + 1 < KSTEPS) {
                const int c16 = 2 * (ks + 1) + lhi;
                #pragma unroll
                for (int mf = 0; mf < 2; ++mf)
                    ldmatrix_x4(afr[nxt][mf], abase[mf] + (((uint32_t)(c16 ^ amask[mf])) << 4));
                #pragma unroll
                for (int j = 0; j < 2; ++j)
                    ldmatrix_x4(bfr[nxt][j], sb + bbase[j] + (((uint32_t)(c16 ^ bmask[j])) << 4));
            }
            #pragma unroll
            for (int mf = 0; mf < 2; ++mf)
                #pragma unroll
                for (int j = 0; j < 2; ++j) {
                    mma_fp8(am[mf][2 * j],     afr[cur][mf], bfr[cur][j][0], bfr[cur][j][2]);
                    mma_fp8(am[mf][2 * j + 1], afr[cur][mf], bfr[cur][j][1], bfr[cur][j][3]);
                }
        }

        // per-chunk column scales (L2-resident, needed only in epilogue)
        float2 c2v[4], i2v[4];
        #pragma unroll
        for (int nf = 0; nf < 4; ++nf) {
            int cg = t * TN + cl0 + nf * 8;
            c2v[nf] = *(const float2*)(g_c2 + cg);
            i2v[nf] = *(const float2*)(g_i2s + cg);
        }

        // ---- phi = exp(-r/(2|sigma|)) with threshold, bf16 into SPHI ----
        #pragma unroll
        for (int mf = 0; mf < 2; ++mf) {
            const int r0 = mrow0 + mf * 16 + g;
            const float xA = x2r[mf * 2], xB = x2r[mf * 2 + 1];
            #pragma unroll
            for (int nf = 0; nf < 4; ++nf) {
                float d0 = am[mf][nf][0], d1 = am[mf][nf][1];
                float d2 = am[mf][nf][2], d3 = am[mf][nf][3];
                float t0 = (xA + c2v[nf].x - 2.f * d0) * i2v[nf].x;
                float t1 = (xA + c2v[nf].y - 2.f * d1) * i2v[nf].y;
                float t2 = (xB + c2v[nf].x - 2.f * d2) * i2v[nf].x;
                float t3 = (xB + c2v[nf].y - 2.f * d3) * i2v[nf].y;
                float p0 = (t0 < 30.f) ? __expf(-t0) : 0.f;
                float p1 = (t1 < 30.f) ? __expf(-t1) : 0.f;
                float p2 = (t2 < 30.f) ? __expf(-t2) : 0.f;
                float p3 = (t3 < 30.f) ? __expf(-t3) : 0.f;
                const int coll = ncol0 + nf * 8 + 2 * (lane & 3);
                *(uint32_t*)(smem + SPHI + (size_t)r0 * PHI_STRIDE + coll * 2)
                    = pack_bf2(p0, p1);
                *(uint32_t*)(smem + SPHI + (size_t)(r0 + 8) * PHI_STRIDE + coll * 2)
                    = pack_bf2(p2, p3);
            }
        }
        __syncthreads();

        // ---- phi @ w^T accumulation (skips everything when phi == 0) ----
        {
            const float* wmat = ((t < 8) ? mean_w : std_w) + (size_t)(ahalf * 16) * KDIM;
            const int wcol0 = (t & 7) * TN + colhalf * 64;
            const char* pbase = smem + SPHI + (size_t)prow * PHI_STRIDE + colhalf * 128;
            #pragma unroll
            for (int i = 0; i < 8; ++i) {
                uint4 u = *(const uint4*)(pbase + i * 16);
                if (u.x | u.y | u.z | u.w) {
                    uint32_t uu[4] = {u.x, u.y, u.z, u.w};
                    #pragma unroll
                    for (int q = 0; q < 4; ++q) {
                        if (!uu[q]) continue;
                        __nv_bfloat162 h = reinterpret_cast<__nv_bfloat162&>(uu[q]);
                        float p0 = __bfloat162float(h.x);
                        float p1 = __bfloat162float(h.y);
                        int c = wcol0 + i * 8 + q * 2;
                        if (p0 != 0.f) {
                            #pragma unroll
                            for (int a = 0; a < ADIM / 2; ++a)
                                acc[a] = fmaf(p0, wmat[(size_t)a * KDIM + c], acc[a]);
                        }
                        if (p1 != 0.f) {
                            #pragma unroll
                            for (int a = 0; a < ADIM / 2; ++a)
                                acc[a] = fmaf(p1, wmat[(size_t)a * KDIM + c + 1], acc[a]);
                        }
                    }
                }
            }
        }

        // ---- end of a net: combine column halves, add bias, write out ----
        if ((t & 7) == 7) {
            const int net = t >> 3;
            #pragma unroll
            for (int a = 0; a < ADIM / 2; ++a)
                acc[a] += __shfl_xor_sync(0xffffffffu, acc[a], 2);
            if (!colhalf) {
                const float* bb = net ? std_b : mean_b;
                float* o = out + ((size_t)blockIdx.x * TM + prow) * (2 * ADIM)
                           + net * ADIM + ahalf * 16;
                #pragma unroll
                for (int a = 0; a < ADIM / 2; ++a) {
                    float v = acc[a] + bb[ahalf * 16 + a];
                    o[a] = net ? __expf(fminf(fmaxf(v, -20.f), 2.f)) : v;
                }
            }
            #pragma unroll
            for (int a = 0; a < ADIM / 2; ++a) acc[a] = 0.f;
        }
    }
}

// ============ launch ============
extern "C" void kernel_launch(void* const* d_in, const int* in_sizes, int n_in,
                              void* d_out, int out_size) {
    const float* obs        = (const float*)d_in[0];
    const float* mean_C     = (const float*)d_in[1];
    const float* mean_sigma = (const float*)d_in[2];
    const float* mean_w     = (const float*)d_in[3];
    const float* mean_b     = (const float*)d_in[4];
    const float* std_C      = (const float*)d_in[5];
    const float* std_sigma  = (const float*)d_in[6];
    const float* std_w      = (const float*)d_in[7];
    const float* std_b      = (const float*)d_in[8];
    float* out = (float*)d_out;

    prep_scales<<<(2 * KDIM * 32) / 256, 256>>>(mean_C, std_C, mean_sigma, std_sigma);

    cudaFuncSetAttribute(rbf_main, cudaFuncAttributeMaxDynamicSharedMemorySize, SMEM_TOTAL);
    rbf_main<<<NBLOCKS, THREADS, SMEM_TOTAL>>>(obs, mean_w, mean_b, std_w, std_b, out);
}

// round 5
// speedup vs baseline: 1.4953x; 1.4953x over previous
#include <cuda_runtime.h>
#include <cuda_bf16.h>
#include <cstdint>

#define BATCH 32768
#define DDIM  256
#define KDIM  1024
#define ADIM  32

#define TM      128
#define TN      128
#define THREADS 512
#define NBLOCKS (BATCH / TM)
#define TOTCH   16          // 2 nets * 8 chunks of 128 centers
#define PHI_STRIDE 272      // bytes per phi row (16B aligned, bank-rotating)

// ---- SMEM layout (bytes) ----
#define SA   0              // A tile 128x256 bf16 swizzled  (65536)
#define SB0  65536          // B tile buf0                    (65536)
#define SB1  131072         // B tile buf1 (reused as phi in slow path)
#define SX2  196608         // x2 per row                     (512)
#define SMEM_TOTAL (196608 + 512)

// ---- device scratch (static, no runtime alloc) ----
__device__ __nv_bfloat16 g_c_bf[(size_t)2 * KDIM * DDIM];  // [mean_C; std_C] bf16
__device__ float g_c2[2 * KDIM];
__device__ float g_i2s[2 * KDIM];

// ============ helpers ============
__device__ __forceinline__ uint32_t smem_u32_of(const void* p) {
    uint32_t a;
    asm("{ .reg .u64 t; cvta.to.shared.u64 t, %1; cvt.u32.u64 %0, t; }" : "=r"(a) : "l"(p));
    return a;
}

__device__ __forceinline__ void ldmatrix_x4(uint32_t& r0, uint32_t& r1, uint32_t& r2,
                                            uint32_t& r3, uint32_t addr) {
    asm volatile("ldmatrix.sync.aligned.m8n8.x4.shared.b16 {%0,%1,%2,%3}, [%4];"
                 : "=r"(r0), "=r"(r1), "=r"(r2), "=r"(r3) : "r"(addr));
}

__device__ __forceinline__ void mma_bf16(float* d, const uint32_t* a, uint32_t b0, uint32_t b1) {
    asm volatile("mma.sync.aligned.m16n8k16.row.col.f32.bf16.bf16.f32 "
                 "{%0,%1,%2,%3}, {%4,%5,%6,%7}, {%8,%9}, {%0,%1,%2,%3};"
                 : "+f"(d[0]), "+f"(d[1]), "+f"(d[2]), "+f"(d[3])
                 : "r"(a[0]), "r"(a[1]), "r"(a[2]), "r"(a[3]), "r"(b0), "r"(b1));
}

#define CP_ASYNC16(dst, src) \
    asm volatile("cp.async.cg.shared.global [%0], [%1], 16;" :: "r"(dst), "l"(src) : "memory")
#define CP_COMMIT()   asm volatile("cp.async.commit_group;" ::: "memory")
#define CP_WAIT_ALL() asm volatile("cp.async.wait_all;" ::: "memory")

__device__ __forceinline__ uint32_t pack_bf2(float lo, float hi) {
    __nv_bfloat162 h = __floats2bfloat162_rn(lo, hi);
    return reinterpret_cast<uint32_t&>(h);
}

// tile byte offset with XOR swizzle on 16B granules (512B rows, 32 granules)
__device__ __forceinline__ uint32_t tile_off(int row, int c16) {
    return ((uint32_t)row << 9) + (((uint32_t)(c16 ^ (row & 7))) << 4);
}

// ============ prep kernel: C -> bf16, c2 = ||c||^2, i2s = 1/(2|sigma|) ============
__global__ void prep_scales(const float* __restrict__ mC, const float* __restrict__ sC,
                            const float* __restrict__ mS, const float* __restrict__ sS) {
    int w = (blockIdx.x * blockDim.x + threadIdx.x) >> 5;
    int lane = threadIdx.x & 31;
    if (w >= 2 * KDIM) return;
    int net = w >> 10, k = w & (KDIM - 1);
    const float* C = net ? sC : mC;
    const float4* cp = (const float4*)(C + (size_t)k * DDIM);
    float4 v0 = cp[lane * 2], v1 = cp[lane * 2 + 1];
    float s = v0.x*v0.x + v0.y*v0.y + v0.z*v0.z + v0.w*v0.w
            + v1.x*v1.x + v1.y*v1.y + v1.z*v1.z + v1.w*v1.w;
    uint4 u;
    u.x = pack_bf2(v0.x, v0.y); u.y = pack_bf2(v0.z, v0.w);
    u.z = pack_bf2(v1.x, v1.y); u.w = pack_bf2(v1.z, v1.w);
    ((uint4*)g_c_bf)[(size_t)w * 32 + lane] = u;
    #pragma unroll
    for (int o = 16; o; o >>= 1) s += __shfl_xor_sync(0xffffffffu, s, o);
    if (lane == 0) {
        g_c2[w] = s;
        float sg = net ? sS[k] : mS[k];
        g_i2s[w] = 1.0f / (2.0f * fabsf(sg));
    }
}

// ============ main kernel ============
__device__ __forceinline__ void issue_B(uint32_t sb, int chunk, int tid) {
    const char* src = (const char*)(g_c_bf + (size_t)chunk * (TN * DDIM));
    #pragma unroll
    for (int it = 0; it < 8; ++it) {
        int i = tid + it * THREADS;          // 4096 granules of 16B
        int row = i >> 5, c16 = i & 31;
        CP_ASYNC16(sb + tile_off(row, c16), src + i * 16);
    }
    CP_COMMIT();
}

__global__ void __launch_bounds__(THREADS, 1)
rbf_main(const float* __restrict__ obs,
         const float* __restrict__ mean_w, const float* __restrict__ mean_b,
         const float* __restrict__ std_w,  const float* __restrict__ std_b,
         float* __restrict__ out) {
    extern __shared__ char smem[];
    const uint32_t su = smem_u32_of(smem);
    const int tid  = threadIdx.x;
    const int lane = tid & 31;
    const int wid  = tid >> 5;
    const int wm   = wid & 3;          // M warp (rows 32*wm)
    const int wn   = wid >> 2;         // N warp (cols 32*wn)
    const int mrow0 = wm * 32;
    const int ncol0 = wn * 32;

    // kick off B(0) loads immediately
    issue_B(su + SB0, 0, tid);

    // ---- A tile: fp32 gmem -> bf16 swizzled SMEM; compute x2 per row ----
    {
        int row = tid >> 2, q = tid & 3;
        const float4* src = (const float4*)(obs + ((size_t)blockIdx.x * TM + row) * DDIM)
                            + q * 16;
        float s = 0.f;
        #pragma unroll
        for (int g = 0; g < 8; ++g) {
            float4 v0 = src[g * 2], v1 = src[g * 2 + 1];
            s += v0.x*v0.x + v0.y*v0.y + v0.z*v0.z + v0.w*v0.w
               + v1.x*v1.x + v1.y*v1.y + v1.z*v1.z + v1.w*v1.w;
            uint4 u;
            u.x = pack_bf2(v0.x, v0.y); u.y = pack_bf2(v0.z, v0.w);
            u.z = pack_bf2(v1.x, v1.y); u.w = pack_bf2(v1.z, v1.w);
            *(uint4*)(smem + SA + tile_off(row, q * 8 + g)) = u;
        }
        s += __shfl_xor_sync(0xffffffffu, s, 1);
        s += __shfl_xor_sync(0xffffffffu, s, 2);
        if (!q) ((float*)(smem + SX2))[row] = s;
    }
    __syncthreads();

    // per-lane x2 values for the 4 row groups this lane's MMA fragments cover
    const int g = lane >> 2;
    float x2r[4];
    {
        const float* sx2 = (const float*)(smem + SX2);
        x2r[0] = sx2[mrow0 + g];
        x2r[1] = sx2[mrow0 + g + 8];
        x2r[2] = sx2[mrow0 + g + 16];
        x2r[3] = sx2[mrow0 + g + 24];
    }

    // precompute per-lane ldmatrix row bases
    const int lhi = lane >> 4;
    uint32_t abase[2]; int amask[2];
    #pragma unroll
    for (int mf = 0; mf < 2; ++mf) {
        int r = mrow0 + mf * 16 + (lane & 15);
        abase[mf] = su + SA + ((uint32_t)r << 9);
        amask[mf] = r & 7;
    }
    int brow[2];
    #pragma unroll
    for (int j = 0; j < 2; ++j) brow[j] = ncol0 + j * 16 + (lane & 15);

    float acc[ADIM / 2];
    #pragma unroll
    for (int a = 0; a < ADIM / 2; ++a) acc[a] = 0.f;

    const int cl0 = ncol0 + 2 * (lane & 3);
    // phi@w partition: each thread = (row, colhalf, ahalf)
    const int prow    = tid >> 2;
    const int ahalf   = tid & 1;
    const int colhalf = (tid >> 1) & 1;

    for (int t = 0; t < TOTCH; ++t) {
        const uint32_t sbOff = (t & 1) ? SB1 : SB0;
        const uint32_t sb = su + sbOff;

        CP_WAIT_ALL();
        __syncthreads();                       // B(t) resident, phi(t-1) consumed
        if (t + 1 < TOTCH) issue_B(su + (((t + 1) & 1) ? SB1 : SB0), t + 1, tid);

        // per-chunk column scales (direct LDG, L2-resident; latency hidden by GEMM)
        float2 c2v[4], i2v[4];
        #pragma unroll
        for (int nf = 0; nf < 4; ++nf) {
            int cg = t * TN + cl0 + nf * 8;
            c2v[nf] = *(const float2*)(g_c2 + cg);
            i2v[nf] = *(const float2*)(g_i2s + cg);
        }

        // ---- GEMM: obs @ C^T for this 32-col warp chunk ----
        float am[2][4][4];
        #pragma unroll
        for (int mf = 0; mf < 2; ++mf)
            #pragma unroll
            for (int nf = 0; nf < 4; ++nf)
                #pragma unroll
                for (int e = 0; e < 4; ++e) am[mf][nf][e] = 0.f;

        #pragma unroll
        for (int k = 0; k < 16; ++k) {
            const int c16 = 2 * k + lhi;
            uint32_t af[2][4];
            #pragma unroll
            for (int mf = 0; mf < 2; ++mf)
                ldmatrix_x4(af[mf][0], af[mf][1], af[mf][2], af[mf][3],
                            abase[mf] + (((uint32_t)(c16 ^ amask[mf])) << 4));
            uint32_t bf[2][4];
            #pragma unroll
            for (int j = 0; j < 2; ++j)
                ldmatrix_x4(bf[j][0], bf[j][1], bf[j][2], bf[j][3],
                            sb + tile_off(brow[j], c16));
            #pragma unroll
            for (int mf = 0; mf < 2; ++mf)
                #pragma unroll
                for (int j = 0; j < 2; ++j) {
                    mma_bf16(am[mf][2 * j],     af[mf], bf[j][0], bf[j][2]);
                    mma_bf16(am[mf][2 * j + 1], af[mf], bf[j][1], bf[j][3]);
                }
        }

        // ---- transform accumulators to tt = r/(2|sigma|) in-place; block-OR test ----
        bool anyp = false;
        #pragma unroll
        for (int mf = 0; mf < 2; ++mf) {
            const float xA = x2r[mf * 2], xB = x2r[mf * 2 + 1];
            #pragma unroll
            for (int nf = 0; nf < 4; ++nf) {
                float t0 = (xA + c2v[nf].x - 2.f * am[mf][nf][0]) * i2v[nf].x;
                float t1 = (xA + c2v[nf].y - 2.f * am[mf][nf][1]) * i2v[nf].y;
                float t2 = (xB + c2v[nf].x - 2.f * am[mf][nf][2]) * i2v[nf].x;
                float t3 = (xB + c2v[nf].y - 2.f * am[mf][nf][3]) * i2v[nf].y;
                am[mf][nf][0] = t0; am[mf][nf][1] = t1;
                am[mf][nf][2] = t2; am[mf][nf][3] = t3;
                anyp |= (t0 < 30.f) | (t1 < 30.f) | (t2 < 30.f) | (t3 < 30.f);
            }
        }
        // barrier doubles as "all warps done reading B(t)"
        int any = __syncthreads_or((int)anyp);

        if (any) {
            // ---- slow path: materialize phi tile in retired B buffer, then phi@w ----
            #pragma unroll
            for (int mf = 0; mf < 2; ++mf) {
                const int r0 = mrow0 + mf * 16 + g;
                #pragma unroll
                for (int nf = 0; nf < 4; ++nf) {
                    float t0 = am[mf][nf][0], t1 = am[mf][nf][1];
                    float t2 = am[mf][nf][2], t3 = am[mf][nf][3];
                    float p0 = (t0 < 30.f) ? __expf(-t0) : 0.f;
                    float p1 = (t1 < 30.f) ? __expf(-t1) : 0.f;
                    float p2 = (t2 < 30.f) ? __expf(-t2) : 0.f;
                    float p3 = (t3 < 30.f) ? __expf(-t3) : 0.f;
                    const int coll = ncol0 + nf * 8 + 2 * (lane & 3);
                    *(uint32_t*)(smem + sbOff + (size_t)r0 * PHI_STRIDE + coll * 2)
                        = pack_bf2(p0, p1);
                    *(uint32_t*)(smem + sbOff + (size_t)(r0 + 8) * PHI_STRIDE + coll * 2)
                        = pack_bf2(p2, p3);
                }
            }
            __syncthreads();

            const float* wmat = ((t < 8) ? mean_w : std_w) + (size_t)(ahalf * 16) * KDIM;
            const int wcol0 = (t & 7) * TN + colhalf * 64;
            const char* pbase = smem + sbOff + (size_t)prow * PHI_STRIDE + colhalf * 128;
            #pragma unroll
            for (int i = 0; i < 8; ++i) {
                uint4 u = *(const uint4*)(pbase + i * 16);
                if (u.x | u.y | u.z | u.w) {
                    uint32_t uu[4] = {u.x, u.y, u.z, u.w};
                    #pragma unroll
                    for (int q = 0; q < 4; ++q) {
                        if (!uu[q]) continue;
                        __nv_bfloat162 h = reinterpret_cast<__nv_bfloat162&>(uu[q]);
                        float p0 = __bfloat162float(h.x);
                        float p1 = __bfloat162float(h.y);
                        int c = wcol0 + i * 8 + q * 2;
                        if (p0 != 0.f) {
                            #pragma unroll
                            for (int a = 0; a < ADIM / 2; ++a)
                                acc[a] = fmaf(p0, wmat[(size_t)a * KDIM + c], acc[a]);
                        }
                        if (p1 != 0.f) {
                            #pragma unroll
                            for (int a = 0; a < ADIM / 2; ++a)
                                acc[a] = fmaf(p1, wmat[(size_t)a * KDIM + c + 1], acc[a]);
                        }
                    }
                }
            }
        }

        // ---- end of a net: combine column halves, add bias, write out ----
        if ((t & 7) == 7) {
            const int net = t >> 3;
            #pragma unroll
            for (int a = 0; a < ADIM / 2; ++a)
                acc[a] += __shfl_xor_sync(0xffffffffu, acc[a], 2);
            if (!colhalf) {
                const float* bb = net ? std_b : mean_b;
                float* o = out + ((size_t)blockIdx.x * TM + prow) * (2 * ADIM)
                           + net * ADIM + ahalf * 16;
                #pragma unroll
                for (int a = 0; a < ADIM / 2; ++a) {
                    float v = acc[a] + bb[ahalf * 16 + a];
                    o[a] = net ? __expf(fminf(fmaxf(v, -20.f), 2.f)) : v;
                }
            }
            #pragma unroll
            for (int a = 0; a < ADIM / 2; ++a) acc[a] = 0.f;
        }
    }
}

// ============ launch ============
extern "C" void kernel_launch(void* const* d_in, const int* in_sizes, int n_in,
                              void* d_out, int out_size) {
    const float* obs        = (const float*)d_in[0];
    const float* mean_C     = (const float*)d_in[1];
    const float* mean_sigma = (const float*)d_in[2];
    const float* mean_w     = (const float*)d_in[3];
    const float* mean_b     = (const float*)d_in[4];
    const float* std_C      = (const float*)d_in[5];
    const float* std_sigma  = (const float*)d_in[6];
    const float* std_w      = (const float*)d_in[7];
    const float* std_b      = (const float*)d_in[8];
    float* out = (float*)d_out;

    prep_scales<<<(2 * KDIM * 32) / 256, 256>>>(mean_C, std_C, mean_sigma, std_sigma);

    cudaFuncSetAttribute(rbf_main, cudaFuncAttributeMaxDynamicSharedMemorySize, SMEM_TOTAL);
    rbf_main<<<NBLOCKS, THREADS, SMEM_TOTAL>>>(obs, mean_w, mean_b, std_w, std_b, out);
}